// round 12
// baseline (speedup 1.0000x reference)
#include <cuda_runtime.h>
#include <cuda_fp16.h>
#include <cstdint>

#define THREADS 256
#define N_TOK   64
#define DIM     96
#define HEADS   6

#define PITCHB  208u    // bytes per smem row (104 fp16; 13*16B, conflict-free LDSM)

// ---- smem planes: q, k, v (single fp16 each; q plane becomes O in-place) ----
#define QH_OFF   0u
#define KP_OFF   13312u
#define VP_OFF   26624u
#define SMEM_BYTES 39936u   // 2 CTAs/SM with room to spare

// ---- prepped globals ----
__device__ uint4  g_qwf4[3456];   // qkv W fragments: 3 slices * 6 kt * 6 np * 32 lanes
__device__ uint4  g_pwf4[1152];   // proj W fragments: 6 kt * 6 np * 32 lanes
__device__ __half g_biash[HEADS * 64 * 64];   // [h][n][m]
__device__ __half g_maskh[512 * 64 * 64];     // [w][n][m] fp16 mask

__device__ __forceinline__ uint32_t packh(float a, float b) {
    __half2 v;
    v.x = __float2half_rn(a);
    v.y = __float2half_rn(b);
    return *reinterpret_cast<uint32_t*>(&v);
}

__global__ void __launch_bounds__(256)
prep_kernel(const float* __restrict__ qkv_w, const float* __restrict__ proj_w,
            const float* __restrict__ rpb, const int* __restrict__ ridx,
            const float* __restrict__ mask, int mask_elems)
{
    int idx = blockIdx.x * 256 + threadIdx.x;
    if (idx < 3456) {
        int lane = idx & 31, np = (idx >> 5) % 6, kt = (idx / 192) % 6, s = idx / 1152;
        int k0 = kt * 16 + (lane & 3) * 2;
        int nc0 = (2 * np) * 8 + (lane >> 2);
        int nc1 = nc0 + 8;
        const float* w0 = qkv_w + s * 96 + nc0;
        const float* w1 = qkv_w + s * 96 + nc1;
        uint4 r;
        r.x = packh(w0[(k0)     * 288], w0[(k0 + 1) * 288]);
        r.y = packh(w0[(k0 + 8) * 288], w0[(k0 + 9) * 288]);
        r.z = packh(w1[(k0)     * 288], w1[(k0 + 1) * 288]);
        r.w = packh(w1[(k0 + 8) * 288], w1[(k0 + 9) * 288]);
        g_qwf4[idx] = r;
    } else if (idx < 4608) {
        int j = idx - 3456;
        int lane = j & 31, np = (j >> 5) % 6, kt = j / 192;
        int k0 = kt * 16 + (lane & 3) * 2;
        int nc0 = (2 * np) * 8 + (lane >> 2);
        int nc1 = nc0 + 8;
        const float* w0 = proj_w + nc0;
        const float* w1 = proj_w + nc1;
        uint4 r;
        r.x = packh(w0[(k0)     * 96], w0[(k0 + 1) * 96]);
        r.y = packh(w0[(k0 + 8) * 96], w0[(k0 + 9) * 96]);
        r.z = packh(w1[(k0)     * 96], w1[(k0 + 1) * 96]);
        r.w = packh(w1[(k0 + 8) * 96], w1[(k0 + 9) * 96]);
        g_pwf4[j] = r;
    } else if (idx < 4608 + 24576) {
        int j = idx - 4608;
        int h = j >> 12, r = (j >> 6) & 63, m = j & 63;
        g_biash[j] = __float2half_rn(rpb[ridx[r * 64 + m] * HEADS + h]);
    } else {
        int j = idx - (4608 + 24576);
        if (j < mask_elems) g_maskh[j] = __float2half_rn(mask[j]);
    }
}

// ---- PTX helpers ----
__device__ __forceinline__ uint32_t smem_u32(const void* p) {
    uint32_t a;
    asm("{ .reg .u64 t; cvta.to.shared.u64 t, %1; cvt.u32.u64 %0, t; }" : "=r"(a) : "l"(p));
    return a;
}
__device__ __forceinline__ void ldsm_x4(uint32_t* r, uint32_t a) {
    asm volatile("ldmatrix.sync.aligned.m8n8.x4.shared.b16 {%0,%1,%2,%3}, [%4];"
        : "=r"(r[0]), "=r"(r[1]), "=r"(r[2]), "=r"(r[3]) : "r"(a));
}
__device__ __forceinline__ void ldsm_x4t(uint32_t* r, uint32_t a) {
    asm volatile("ldmatrix.sync.aligned.m8n8.x4.trans.shared.b16 {%0,%1,%2,%3}, [%4];"
        : "=r"(r[0]), "=r"(r[1]), "=r"(r[2]), "=r"(r[3]) : "r"(a));
}
__device__ __forceinline__ void mma_h(float* c, const uint32_t* a,
                                      uint32_t b0, uint32_t b1) {
    asm volatile("mma.sync.aligned.m16n8k16.row.col.f32.f16.f16.f32 "
        "{%0,%1,%2,%3}, {%4,%5,%6,%7}, {%8,%9}, {%0,%1,%2,%3};"
        : "+f"(c[0]), "+f"(c[1]), "+f"(c[2]), "+f"(c[3])
        : "r"(a[0]), "r"(a[1]), "r"(a[2]), "r"(a[3]), "r"(b0), "r"(b1));
}

extern __shared__ char smc[];

__global__ void __launch_bounds__(THREADS, 2)
win_attn_mma(const float* __restrict__ x,
             const float* __restrict__ qkv_b,
             const float* __restrict__ proj_b,
             float* __restrict__ out,
             int nW)
{
    const int t = threadIdx.x, wid = t >> 5, lane = t & 31, b = blockIdx.x;
    const uint32_t sb = smem_u32(smc);
    const int mt = wid & 3;      // m tile 0..3
    const int g6 = wid >> 2;     // n group 0..1

    // ---- load A fragments (x) from gmem, single fp16 ----
    uint32_t xah[6][4];
    {
        const float* xb = x + (size_t)b * 6144;
        const int gr = lane >> 2, ck = (lane & 3) * 2;
        const float* base = xb + (size_t)(mt * 16 + gr) * 96 + ck;
        #pragma unroll
        for (int kt = 0; kt < 6; kt++) {
            float2 v00 = *(const float2*)(base + kt * 16);
            float2 v10 = *(const float2*)(base + kt * 16 + 8 * 96);
            float2 v01 = *(const float2*)(base + kt * 16 + 8);
            float2 v11 = *(const float2*)(base + kt * 16 + 8 * 96 + 8);
            xah[kt][0] = packh(v00.x, v00.y);
            xah[kt][1] = packh(v10.x, v10.y);
            xah[kt][2] = packh(v01.x, v01.y);
            xah[kt][3] = packh(v11.x, v11.y);
        }
    }
    const int r0 = mt * 16 + (lane >> 2);

    // ---- qkv GEMM: 3 slices, single-term A, B single fp16 ----
    #pragma unroll 1
    for (int s = 0; s < 3; s++) {
        float acc[6][4];
        #pragma unroll
        for (int j = 0; j < 6; j++)
            { acc[j][0] = 0.f; acc[j][1] = 0.f; acc[j][2] = 0.f; acc[j][3] = 0.f; }
        #pragma unroll
        for (int kt = 0; kt < 6; kt++) {
            #pragma unroll
            for (int jp = 0; jp < 3; jp++) {
                int fi = ((s * 6 + kt) * 6 + g6 * 3 + jp) * 32 + lane;
                uint4 w = g_qwf4[fi];
                mma_h(acc[2*jp],   xah[kt], w.x, w.y);
                mma_h(acc[2*jp+1], xah[kt], w.z, w.w);
            }
        }
        const float scl = (s == 0) ? 0.25f : 1.0f;
        const uint32_t pofs = (s == 0) ? QH_OFF : ((s == 1) ? KP_OFF : VP_OFF);
        #pragma unroll
        for (int j = 0; j < 6; j++) {
            int c0 = (g6 * 6 + j) * 8 + (lane & 3) * 2;
            float b0 = __ldg(qkv_b + s * 96 + c0), b1 = __ldg(qkv_b + s * 96 + c0 + 1);
            uint32_t off = (uint32_t)r0 * PITCHB + c0 * 2;
            *(uint32_t*)(smc + pofs + off) =
                packh((acc[j][0] + b0) * scl, (acc[j][1] + b1) * scl);
            *(uint32_t*)(smc + pofs + off + 8 * PITCHB) =
                packh((acc[j][2] + b0) * scl, (acc[j][3] + b1) * scl);
        }
    }
    __syncthreads();   // q/k/v complete

    // ---- attention: warp handles heads g6, g6+2, g6+4 on its mt tile ----
    const __half* maskh = g_maskh + (size_t)(b % nW) * 4096;
    uint32_t oah[3][4];              // own O tiles in proj-A fragment form
    #pragma unroll 1
    for (int iu = 0; iu < 3; iu++) {
        const int h = g6 + 2 * iu;

        uint32_t qhf[4];
        {
            uint32_t ar = (uint32_t)(mt * 16 + (lane & 15)) * PITCHB
                        + (uint32_t)(h * 16 + ((lane >> 4) << 3)) * 2;
            ldsm_x4(qhf, sb + QH_OFF + ar);
        }
        float s8[8][4];
        #pragma unroll
        for (int ntp = 0; ntp < 4; ntp++) {
            uint32_t kh[4];
            uint32_t br = (uint32_t)(ntp * 16 + (lane & 15)) * PITCHB
                        + (uint32_t)(h * 16 + ((lane >> 4) << 3)) * 2;
            ldsm_x4(kh, sb + KP_OFF + br);
            #pragma unroll
            for (int half = 0; half < 2; half++) {
                int nt = 2 * ntp + half;
                s8[nt][0] = 0.f; s8[nt][1] = 0.f; s8[nt][2] = 0.f; s8[nt][3] = 0.f;
                mma_h(s8[nt], qhf, kh[half], kh[half + 2]);
            }
        }
        // + (bias + mask) via fused half2 adds
        {
            const uint32_t* br0 = (const uint32_t*)(g_biash + (size_t)(h * 64 + r0) * 64);
            const uint32_t* br1 = (const uint32_t*)(g_biash + (size_t)(h * 64 + r0 + 8) * 64);
            const uint32_t* mr0 = (const uint32_t*)(maskh + (size_t)r0 * 64);
            const uint32_t* mr1 = (const uint32_t*)(maskh + (size_t)(r0 + 8) * 64);
            int ci = lane & 3;
            #pragma unroll
            for (int nt = 0; nt < 8; nt++) {
                uint32_t bw = br0[nt * 4 + ci], mw = mr0[nt * 4 + ci];
                __half2 sm = __hadd2(*reinterpret_cast<__half2*>(&bw),
                                     *reinterpret_cast<__half2*>(&mw));
                float2 bb = __half22float2(sm);
                s8[nt][0] += bb.x; s8[nt][1] += bb.y;
                bw = br1[nt * 4 + ci]; mw = mr1[nt * 4 + ci];
                sm = __hadd2(*reinterpret_cast<__half2*>(&bw),
                             *reinterpret_cast<__half2*>(&mw));
                bb = __half22float2(sm);
                s8[nt][2] += bb.x; s8[nt][3] += bb.y;
            }
        }
        // softmax (register + shfl over lane%4 group)
        float mx0 = -1e30f, mx1 = -1e30f;
        #pragma unroll
        for (int nt = 0; nt < 8; nt++) {
            mx0 = fmaxf(mx0, fmaxf(s8[nt][0], s8[nt][1]));
            mx1 = fmaxf(mx1, fmaxf(s8[nt][2], s8[nt][3]));
        }
        mx0 = fmaxf(mx0, __shfl_xor_sync(0xffffffffu, mx0, 1));
        mx0 = fmaxf(mx0, __shfl_xor_sync(0xffffffffu, mx0, 2));
        mx1 = fmaxf(mx1, __shfl_xor_sync(0xffffffffu, mx1, 1));
        mx1 = fmaxf(mx1, __shfl_xor_sync(0xffffffffu, mx1, 2));
        float sum0 = 0.f, sum1 = 0.f;
        #pragma unroll
        for (int nt = 0; nt < 8; nt++) {
            s8[nt][0] = __expf(s8[nt][0] - mx0); sum0 += s8[nt][0];
            s8[nt][1] = __expf(s8[nt][1] - mx0); sum0 += s8[nt][1];
            s8[nt][2] = __expf(s8[nt][2] - mx1); sum1 += s8[nt][2];
            s8[nt][3] = __expf(s8[nt][3] - mx1); sum1 += s8[nt][3];
        }
        sum0 += __shfl_xor_sync(0xffffffffu, sum0, 1);
        sum0 += __shfl_xor_sync(0xffffffffu, sum0, 2);
        sum1 += __shfl_xor_sync(0xffffffffu, sum1, 1);
        sum1 += __shfl_xor_sync(0xffffffffu, sum1, 2);
        float inv0 = 1.f / sum0, inv1 = 1.f / sum1;
        #pragma unroll
        for (int nt = 0; nt < 8; nt++) {
            s8[nt][0] *= inv0; s8[nt][1] *= inv0;
            s8[nt][2] *= inv1; s8[nt][3] *= inv1;
        }
        // PV: O(16x16) = P(16x64) @ V(64x16); P,V single fp16
        float o[2][4];
        o[0][0]=0.f;o[0][1]=0.f;o[0][2]=0.f;o[0][3]=0.f;
        o[1][0]=0.f;o[1][1]=0.f;o[1][2]=0.f;o[1][3]=0.f;
        #pragma unroll
        for (int kt = 0; kt < 4; kt++) {
            uint32_t pa[4];
            pa[0] = packh(s8[2*kt][0],   s8[2*kt][1]);
            pa[1] = packh(s8[2*kt][2],   s8[2*kt][3]);
            pa[2] = packh(s8[2*kt+1][0], s8[2*kt+1][1]);
            pa[3] = packh(s8[2*kt+1][2], s8[2*kt+1][3]);
            uint32_t vr = (uint32_t)(kt * 16 + (lane & 15)) * PITCHB
                        + (uint32_t)(h * 16 + ((lane >> 4) << 3)) * 2;
            uint32_t vh[4];
            ldsm_x4t(vh, sb + VP_OFF + vr);
            mma_h(o[0], pa, vh[0], vh[1]);
            mma_h(o[1], pa, vh[2], vh[3]);
        }
        // O single fp16: keep in regs AND store into dead q tile
        #pragma unroll
        for (int nt2 = 0; nt2 < 2; nt2++) {
            int c0 = h * 16 + nt2 * 8 + (lane & 3) * 2;
            uint32_t p0 = packh(o[nt2][0], o[nt2][1]);
            uint32_t p1 = packh(o[nt2][2], o[nt2][3]);
            oah[iu][nt2*2]   = p0;
            oah[iu][nt2*2+1] = p1;
            uint32_t off = (uint32_t)r0 * PITCHB + c0 * 2;
            *(uint32_t*)(smc + QH_OFF + off)              = p0;
            *(uint32_t*)(smc + QH_OFF + off + 8 * PITCHB) = p1;
        }
    }
    __syncthreads();   // O complete in QH plane

    // ---- proj GEMM: A = O single fp16 (own tiles in regs, partner via ldsm) ----
    {
        float acc[6][4];
        #pragma unroll
        for (int j = 0; j < 6; j++)
            { acc[j][0] = 0.f; acc[j][1] = 0.f; acc[j][2] = 0.f; acc[j][3] = 0.f; }
        #pragma unroll
        for (int kt = 0; kt < 6; kt++) {
            uint32_t ah[4];
            if ((kt & 1) == g6) {
                int iu = kt >> 1;
                ah[0] = oah[iu][0]; ah[1] = oah[iu][1]; ah[2] = oah[iu][2]; ah[3] = oah[iu][3];
            } else {
                uint32_t ar = (uint32_t)(mt * 16 + (lane & 15)) * PITCHB
                            + (uint32_t)(kt * 16 + ((lane >> 4) << 3)) * 2;
                ldsm_x4(ah, sb + QH_OFF + ar);
            }
            #pragma unroll
            for (int jp = 0; jp < 3; jp++) {
                int fi = (kt * 6 + g6 * 3 + jp) * 32 + lane;
                uint4 w = g_pwf4[fi];
                mma_h(acc[2*jp],   ah, w.x, w.y);
                mma_h(acc[2*jp+1], ah, w.z, w.w);
            }
        }
        float* ob = out + (size_t)b * 6144;
        #pragma unroll
        for (int j = 0; j < 6; j++) {
            int c0 = (g6 * 6 + j) * 8 + (lane & 3) * 2;
            float b0 = __ldg(proj_b + c0), b1 = __ldg(proj_b + c0 + 1);
            *(float2*)(ob + (size_t)r0 * 96 + c0) =
                make_float2(acc[j][0] + b0, acc[j][1] + b1);
            *(float2*)(ob + (size_t)(r0 + 8) * 96 + c0) =
                make_float2(acc[j][2] + b0, acc[j][3] + b1);
        }
    }
}

extern "C" void kernel_launch(void* const* d_in, const int* in_sizes, int n_in,
                              void* d_out, int out_size) {
    const float* x      = (const float*)d_in[0];
    const float* mask   = (const float*)d_in[1];
    const float* qkv_w  = (const float*)d_in[2];
    const float* qkv_b  = (const float*)d_in[3];
    const float* proj_w = (const float*)d_in[4];
    const float* proj_b = (const float*)d_in[5];
    const float* rpb    = (const float*)d_in[6];
    const int*   ridx   = (const int*)d_in[7];
    float* out = (float*)d_out;

    const int B_ = in_sizes[0] / (N_TOK * DIM);        // 8192
    const int nW = in_sizes[1] / (N_TOK * N_TOK);      // 512
    const int mask_elems = in_sizes[1];                // nW*4096

    int prep_total = 4608 + 24576 + mask_elems;
    prep_kernel<<<(prep_total + 255) / 256, 256>>>(qkv_w, proj_w, rpb, ridx,
                                                   mask, mask_elems);

    cudaFuncSetAttribute(win_attn_mma,
                         cudaFuncAttributeMaxDynamicSharedMemorySize, SMEM_BYTES);
    win_attn_mma<<<B_, THREADS, SMEM_BYTES>>>(x, qkv_b, proj_b, out, nW);
}

// round 13
// speedup vs baseline: 1.4167x; 1.4167x over previous
#include <cuda_runtime.h>
#include <cuda_fp16.h>
#include <cstdint>

#define THREADS 256
#define N_TOK   64
#define DIM     96
#define HEADS   6

#define PITCHB  208u    // bytes per smem row (104 fp16; 13*16B, conflict-free LDSM)

// ---- smem planes: q, k, v (single fp16 each; q plane becomes O in-place) ----
#define QH_OFF   0u
#define KP_OFF   13312u
#define VP_OFF   26624u
#define SMEM_BYTES 39936u   // 2 CTAs/SM

// ---- prepped globals (all in mma-fragment order) ----
__device__ uint4 g_qwf4[3456];            // qkv W: 3 slices * 6 kt * 6 np * 32 lanes
__device__ uint4 g_pwf4[1152];            // proj W: 6 kt * 6 np * 32 lanes
__device__ uint2 g_biasf[HEADS * 4 * 8 * 32];   // [(h*4+mt)*8+nt][lane]
__device__ uint2 g_maskf[512 * 4 * 8 * 32];     // [(w*4+mt)*8+nt][lane]

__device__ __forceinline__ uint32_t packh(float a, float b) {
    __half2 v;
    v.x = __float2half_rn(a);
    v.y = __float2half_rn(b);
    return *reinterpret_cast<uint32_t*>(&v);
}

__global__ void __launch_bounds__(256)
prep_kernel(const float* __restrict__ qkv_w, const float* __restrict__ proj_w,
            const float* __restrict__ rpb, const int* __restrict__ ridx,
            const float* __restrict__ mask, int nW)
{
    int idx = blockIdx.x * 256 + threadIdx.x;
    if (idx < 3456) {
        int lane = idx & 31, np = (idx >> 5) % 6, kt = (idx / 192) % 6, s = idx / 1152;
        int k0 = kt * 16 + (lane & 3) * 2;
        int nc0 = (2 * np) * 8 + (lane >> 2);
        int nc1 = nc0 + 8;
        const float* w0 = qkv_w + s * 96 + nc0;
        const float* w1 = qkv_w + s * 96 + nc1;
        uint4 r;
        r.x = packh(w0[(k0)     * 288], w0[(k0 + 1) * 288]);
        r.y = packh(w0[(k0 + 8) * 288], w0[(k0 + 9) * 288]);
        r.z = packh(w1[(k0)     * 288], w1[(k0 + 1) * 288]);
        r.w = packh(w1[(k0 + 8) * 288], w1[(k0 + 9) * 288]);
        g_qwf4[idx] = r;
    } else if (idx < 4608) {
        int j = idx - 3456;
        int lane = j & 31, np = (j >> 5) % 6, kt = j / 192;
        int k0 = kt * 16 + (lane & 3) * 2;
        int nc0 = (2 * np) * 8 + (lane >> 2);
        int nc1 = nc0 + 8;
        const float* w0 = proj_w + nc0;
        const float* w1 = proj_w + nc1;
        uint4 r;
        r.x = packh(w0[(k0)     * 96], w0[(k0 + 1) * 96]);
        r.y = packh(w0[(k0 + 8) * 96], w0[(k0 + 9) * 96]);
        r.z = packh(w1[(k0)     * 96], w1[(k0 + 1) * 96]);
        r.w = packh(w1[(k0 + 8) * 96], w1[(k0 + 9) * 96]);
        g_pwf4[j] = r;
    } else if (idx < 4608 + 6144) {
        // bias fragments: j = ((h*4+mt)*8+nt)*32+lane
        int j = idx - 4608;
        int lane = j & 31, nt = (j >> 5) & 7, mt = (j >> 8) & 3, h = j >> 10;
        int r0 = mt * 16 + (lane >> 2);
        int c0 = nt * 8 + (lane & 3) * 2;
        float b00 = rpb[ridx[(r0)     * 64 + c0]     * HEADS + h];
        float b01 = rpb[ridx[(r0)     * 64 + c0 + 1] * HEADS + h];
        float b10 = rpb[ridx[(r0 + 8) * 64 + c0]     * HEADS + h];
        float b11 = rpb[ridx[(r0 + 8) * 64 + c0 + 1] * HEADS + h];
        uint2 r;
        r.x = packh(b00, b01);
        r.y = packh(b10, b11);
        g_biasf[j] = r;
    } else {
        // mask fragments: j = ((w*4+mt)*8+nt)*32+lane
        int j = idx - (4608 + 6144);
        if (j < nW * 1024) {
            int lane = j & 31, nt = (j >> 5) & 7, mt = (j >> 8) & 3, w = j >> 10;
            int r0 = mt * 16 + (lane >> 2);
            int c0 = nt * 8 + (lane & 3) * 2;
            const float* mb = mask + (size_t)w * 4096;
            float2 a = *(const float2*)(mb + (size_t)r0 * 64 + c0);
            float2 c = *(const float2*)(mb + (size_t)(r0 + 8) * 64 + c0);
            uint2 r;
            r.x = packh(a.x, a.y);
            r.y = packh(c.x, c.y);
            g_maskf[j] = r;
        }
    }
}

// ---- PTX helpers ----
__device__ __forceinline__ uint32_t smem_u32(const void* p) {
    uint32_t a;
    asm("{ .reg .u64 t; cvta.to.shared.u64 t, %1; cvt.u32.u64 %0, t; }" : "=r"(a) : "l"(p));
    return a;
}
__device__ __forceinline__ void ldsm_x4(uint32_t* r, uint32_t a) {
    asm volatile("ldmatrix.sync.aligned.m8n8.x4.shared.b16 {%0,%1,%2,%3}, [%4];"
        : "=r"(r[0]), "=r"(r[1]), "=r"(r[2]), "=r"(r[3]) : "r"(a));
}
__device__ __forceinline__ void ldsm_x4t(uint32_t* r, uint32_t a) {
    asm volatile("ldmatrix.sync.aligned.m8n8.x4.trans.shared.b16 {%0,%1,%2,%3}, [%4];"
        : "=r"(r[0]), "=r"(r[1]), "=r"(r[2]), "=r"(r[3]) : "r"(a));
}
__device__ __forceinline__ void mma_h(float* c, const uint32_t* a,
                                      uint32_t b0, uint32_t b1) {
    asm volatile("mma.sync.aligned.m16n8k16.row.col.f32.f16.f16.f32 "
        "{%0,%1,%2,%3}, {%4,%5,%6,%7}, {%8,%9}, {%0,%1,%2,%3};"
        : "+f"(c[0]), "+f"(c[1]), "+f"(c[2]), "+f"(c[3])
        : "r"(a[0]), "r"(a[1]), "r"(a[2]), "r"(a[3]), "r"(b0), "r"(b1));
}

extern __shared__ char smc[];

__global__ void __launch_bounds__(THREADS, 2)
win_attn_mma(const float* __restrict__ x,
             const float* __restrict__ qkv_b,
             const float* __restrict__ proj_b,
             float* __restrict__ out,
             int nW)
{
    const int t = threadIdx.x, wid = t >> 5, lane = t & 31, b = blockIdx.x;
    const uint32_t sb = smem_u32(smc);
    const int mt = wid & 3;      // m tile 0..3
    const int g6 = wid >> 2;     // n group 0..1

    // ---- load A fragments (x) from gmem, single fp16 ----
    uint32_t xah[6][4];
    {
        const float* xb = x + (size_t)b * 6144;
        const int gr = lane >> 2, ck = (lane & 3) * 2;
        const float* base = xb + (size_t)(mt * 16 + gr) * 96 + ck;
        #pragma unroll
        for (int kt = 0; kt < 6; kt++) {
            float2 v00 = *(const float2*)(base + kt * 16);
            float2 v10 = *(const float2*)(base + kt * 16 + 8 * 96);
            float2 v01 = *(const float2*)(base + kt * 16 + 8);
            float2 v11 = *(const float2*)(base + kt * 16 + 8 * 96 + 8);
            xah[kt][0] = packh(v00.x, v00.y);
            xah[kt][1] = packh(v10.x, v10.y);
            xah[kt][2] = packh(v01.x, v01.y);
            xah[kt][3] = packh(v11.x, v11.y);
        }
    }
    const int r0 = mt * 16 + (lane >> 2);

    // ---- qkv GEMM: 3 slices, single-term A, B single fp16 ----
    #pragma unroll 1
    for (int s = 0; s < 3; s++) {
        float acc[6][4];
        #pragma unroll
        for (int j = 0; j < 6; j++)
            { acc[j][0] = 0.f; acc[j][1] = 0.f; acc[j][2] = 0.f; acc[j][3] = 0.f; }
        #pragma unroll
        for (int kt = 0; kt < 6; kt++) {
            #pragma unroll
            for (int jp = 0; jp < 3; jp++) {
                int fi = ((s * 6 + kt) * 6 + g6 * 3 + jp) * 32 + lane;
                uint4 w = g_qwf4[fi];
                mma_h(acc[2*jp],   xah[kt], w.x, w.y);
                mma_h(acc[2*jp+1], xah[kt], w.z, w.w);
            }
        }
        const float scl = (s == 0) ? 0.25f : 1.0f;
        const uint32_t pofs = (s == 0) ? QH_OFF : ((s == 1) ? KP_OFF : VP_OFF);
        #pragma unroll
        for (int j = 0; j < 6; j++) {
            int c0 = (g6 * 6 + j) * 8 + (lane & 3) * 2;
            float b0 = __ldg(qkv_b + s * 96 + c0), b1 = __ldg(qkv_b + s * 96 + c0 + 1);
            uint32_t off = (uint32_t)r0 * PITCHB + c0 * 2;
            *(uint32_t*)(smc + pofs + off) =
                packh((acc[j][0] + b0) * scl, (acc[j][1] + b1) * scl);
            *(uint32_t*)(smc + pofs + off + 8 * PITCHB) =
                packh((acc[j][2] + b0) * scl, (acc[j][3] + b1) * scl);
        }
    }
    __syncthreads();   // q/k/v complete

    // ---- preload mask fragments (h-independent, reused across 3 units) ----
    uint2 mreg[8];
    {
        const uint2* mfp = g_maskf + ((size_t)(b % nW) * 4 + mt) * 256 + lane;
        #pragma unroll
        for (int nt = 0; nt < 8; nt++) mreg[nt] = mfp[nt * 32];
    }

    // ---- attention: warp handles heads g6, g6+2, g6+4 on its mt tile ----
    uint32_t oah[3][4];              // own O tiles in proj-A fragment form
    #pragma unroll 1
    for (int iu = 0; iu < 3; iu++) {
        const int h = g6 + 2 * iu;

        uint32_t qhf[4];
        {
            uint32_t ar = (uint32_t)(mt * 16 + (lane & 15)) * PITCHB
                        + (uint32_t)(h * 16 + ((lane >> 4) << 3)) * 2;
            ldsm_x4(qhf, sb + QH_OFF + ar);
        }
        float s8[8][4];
        #pragma unroll
        for (int ntp = 0; ntp < 4; ntp++) {
            uint32_t kh[4];
            uint32_t br = (uint32_t)(ntp * 16 + (lane & 15)) * PITCHB
                        + (uint32_t)(h * 16 + ((lane >> 4) << 3)) * 2;
            ldsm_x4(kh, sb + KP_OFF + br);
            #pragma unroll
            for (int half = 0; half < 2; half++) {
                int nt = 2 * ntp + half;
                s8[nt][0] = 0.f; s8[nt][1] = 0.f; s8[nt][2] = 0.f; s8[nt][3] = 0.f;
                mma_h(s8[nt], qhf, kh[half], kh[half + 2]);
            }
        }
        // + (bias + mask), both fragment-ordered
        {
            const uint2* bfp = g_biasf + ((size_t)h * 4 + mt) * 256 + lane;
            #pragma unroll
            for (int nt = 0; nt < 8; nt++) {
                uint2 bw = bfp[nt * 32];
                __half2 s0 = __hadd2(*reinterpret_cast<__half2*>(&bw.x),
                                     *reinterpret_cast<__half2*>(&mreg[nt].x));
                __half2 s1 = __hadd2(*reinterpret_cast<__half2*>(&bw.y),
                                     *reinterpret_cast<__half2*>(&mreg[nt].y));
                float2 f0 = __half22float2(s0);
                float2 f1 = __half22float2(s1);
                s8[nt][0] += f0.x; s8[nt][1] += f0.y;
                s8[nt][2] += f1.x; s8[nt][3] += f1.y;
            }
        }
        // softmax (register + shfl over lane%4 group)
        float mx0 = -1e30f, mx1 = -1e30f;
        #pragma unroll
        for (int nt = 0; nt < 8; nt++) {
            mx0 = fmaxf(mx0, fmaxf(s8[nt][0], s8[nt][1]));
            mx1 = fmaxf(mx1, fmaxf(s8[nt][2], s8[nt][3]));
        }
        mx0 = fmaxf(mx0, __shfl_xor_sync(0xffffffffu, mx0, 1));
        mx0 = fmaxf(mx0, __shfl_xor_sync(0xffffffffu, mx0, 2));
        mx1 = fmaxf(mx1, __shfl_xor_sync(0xffffffffu, mx1, 1));
        mx1 = fmaxf(mx1, __shfl_xor_sync(0xffffffffu, mx1, 2));
        float sum0 = 0.f, sum1 = 0.f;
        #pragma unroll
        for (int nt = 0; nt < 8; nt++) {
            s8[nt][0] = __expf(s8[nt][0] - mx0); sum0 += s8[nt][0];
            s8[nt][1] = __expf(s8[nt][1] - mx0); sum0 += s8[nt][1];
            s8[nt][2] = __expf(s8[nt][2] - mx1); sum1 += s8[nt][2];
            s8[nt][3] = __expf(s8[nt][3] - mx1); sum1 += s8[nt][3];
        }
        sum0 += __shfl_xor_sync(0xffffffffu, sum0, 1);
        sum0 += __shfl_xor_sync(0xffffffffu, sum0, 2);
        sum1 += __shfl_xor_sync(0xffffffffu, sum1, 1);
        sum1 += __shfl_xor_sync(0xffffffffu, sum1, 2);
        float inv0 = 1.f / sum0, inv1 = 1.f / sum1;
        #pragma unroll
        for (int nt = 0; nt < 8; nt++) {
            s8[nt][0] *= inv0; s8[nt][1] *= inv0;
            s8[nt][2] *= inv1; s8[nt][3] *= inv1;
        }
        // PV: O(16x16) = P(16x64) @ V(64x16); P,V single fp16
        float o[2][4];
        o[0][0]=0.f;o[0][1]=0.f;o[0][2]=0.f;o[0][3]=0.f;
        o[1][0]=0.f;o[1][1]=0.f;o[1][2]=0.f;o[1][3]=0.f;
        #pragma unroll
        for (int kt = 0; kt < 4; kt++) {
            uint32_t pa[4];
            pa[0] = packh(s8[2*kt][0],   s8[2*kt][1]);
            pa[1] = packh(s8[2*kt][2],   s8[2*kt][3]);
            pa[2] = packh(s8[2*kt+1][0], s8[2*kt+1][1]);
            pa[3] = packh(s8[2*kt+1][2], s8[2*kt+1][3]);
            uint32_t vr = (uint32_t)(kt * 16 + (lane & 15)) * PITCHB
                        + (uint32_t)(h * 16 + ((lane >> 4) << 3)) * 2;
            uint32_t vh[4];
            ldsm_x4t(vh, sb + VP_OFF + vr);
            mma_h(o[0], pa, vh[0], vh[1]);
            mma_h(o[1], pa, vh[2], vh[3]);
        }
        // O single fp16: keep in regs AND store into dead q tile
        #pragma unroll
        for (int nt2 = 0; nt2 < 2; nt2++) {
            int c0 = h * 16 + nt2 * 8 + (lane & 3) * 2;
            uint32_t p0 = packh(o[nt2][0], o[nt2][1]);
            uint32_t p1 = packh(o[nt2][2], o[nt2][3]);
            oah[iu][nt2*2]   = p0;
            oah[iu][nt2*2+1] = p1;
            uint32_t off = (uint32_t)r0 * PITCHB + c0 * 2;
            *(uint32_t*)(smc + QH_OFF + off)              = p0;
            *(uint32_t*)(smc + QH_OFF + off + 8 * PITCHB) = p1;
        }
    }
    __syncthreads();   // O complete in QH plane

    // ---- proj GEMM: A = O single fp16 (own tiles in regs, partner via ldsm) ----
    {
        float acc[6][4];
        #pragma unroll
        for (int j = 0; j < 6; j++)
            { acc[j][0] = 0.f; acc[j][1] = 0.f; acc[j][2] = 0.f; acc[j][3] = 0.f; }
        #pragma unroll
        for (int kt = 0; kt < 6; kt++) {
            uint32_t ah[4];
            if ((kt & 1) == g6) {
                int iu = kt >> 1;
                ah[0] = oah[iu][0]; ah[1] = oah[iu][1]; ah[2] = oah[iu][2]; ah[3] = oah[iu][3];
            } else {
                uint32_t ar = (uint32_t)(mt * 16 + (lane & 15)) * PITCHB
                            + (uint32_t)(kt * 16 + ((lane >> 4) << 3)) * 2;
                ldsm_x4(ah, sb + QH_OFF + ar);
            }
            #pragma unroll
            for (int jp = 0; jp < 3; jp++) {
                int fi = (kt * 6 + g6 * 3 + jp) * 32 + lane;
                uint4 w = g_pwf4[fi];
                mma_h(acc[2*jp],   ah, w.x, w.y);
                mma_h(acc[2*jp+1], ah, w.z, w.w);
            }
        }
        float* ob = out + (size_t)b * 6144;
        #pragma unroll
        for (int j = 0; j < 6; j++) {
            int c0 = (g6 * 6 + j) * 8 + (lane & 3) * 2;
            float b0 = __ldg(proj_b + c0), b1 = __ldg(proj_b + c0 + 1);
            *(float2*)(ob + (size_t)r0 * 96 + c0) =
                make_float2(acc[j][0] + b0, acc[j][1] + b1);
            *(float2*)(ob + (size_t)(r0 + 8) * 96 + c0) =
                make_float2(acc[j][2] + b0, acc[j][3] + b1);
        }
    }
}

extern "C" void kernel_launch(void* const* d_in, const int* in_sizes, int n_in,
                              void* d_out, int out_size) {
    const float* x      = (const float*)d_in[0];
    const float* mask   = (const float*)d_in[1];
    const float* qkv_w  = (const float*)d_in[2];
    const float* qkv_b  = (const float*)d_in[3];
    const float* proj_w = (const float*)d_in[4];
    const float* proj_b = (const float*)d_in[5];
    const float* rpb    = (const float*)d_in[6];
    const int*   ridx   = (const int*)d_in[7];
    float* out = (float*)d_out;

    const int B_ = in_sizes[0] / (N_TOK * DIM);        // 8192
    const int nW = in_sizes[1] / (N_TOK * N_TOK);      // 512

    int prep_total = 4608 + 6144 + nW * 1024;
    prep_kernel<<<(prep_total + 255) / 256, 256>>>(qkv_w, proj_w, rpb, ridx,
                                                   mask, nW);

    cudaFuncSetAttribute(win_attn_mma,
                         cudaFuncAttributeMaxDynamicSharedMemorySize, SMEM_BYTES);
    win_attn_mma<<<B_, THREADS, SMEM_BYTES>>>(x, qkv_b, proj_b, out, nW);
}

// round 14
// speedup vs baseline: 1.4465x; 1.0210x over previous
#include <cuda_runtime.h>
#include <cuda_fp16.h>
#include <cstdint>

#define THREADS 256
#define N_TOK   64
#define DIM     96
#define HEADS   6

#define PITCHB  208u    // bytes per smem row (104 fp16; 13*16B, conflict-free LDSM)

// ---- smem planes: O-exchange, k, v (single fp16 each) ----
#define OP_OFF   0u
#define KP_OFF   13312u
#define VP_OFF   26624u
#define SMEM_BYTES 39936u   // 2 CTAs/SM

// ---- prepped globals (all in mma-fragment order) ----
__device__ uint4 g_qwf4[3456];            // qkv W: 3 slices * 6 kt * 6 np * 32 lanes (q slice pre-scaled 0.25)
__device__ uint4 g_pwf4[1152];            // proj W: 6 kt * 6 np * 32 lanes
__device__ uint2 g_biasf[HEADS * 4 * 8 * 32];   // [(h*4+mt)*8+nt][lane]
__device__ uint2 g_maskf[512 * 4 * 8 * 32];     // [(w*4+mt)*8+nt][lane]

__device__ __forceinline__ uint32_t packh(float a, float b) {
    __half2 v;
    v.x = __float2half_rn(a);
    v.y = __float2half_rn(b);
    return *reinterpret_cast<uint32_t*>(&v);
}

__global__ void __launch_bounds__(256)
prep_kernel(const float* __restrict__ qkv_w, const float* __restrict__ proj_w,
            const float* __restrict__ rpb, const int* __restrict__ ridx,
            const float* __restrict__ mask, int nW)
{
    int idx = blockIdx.x * 256 + threadIdx.x;
    if (idx < 3456) {
        int lane = idx & 31, np = (idx >> 5) % 6, kt = (idx / 192) % 6, s = idx / 1152;
        int k0 = kt * 16 + (lane & 3) * 2;
        int nc0 = (2 * np) * 8 + (lane >> 2);
        int nc1 = nc0 + 8;
        const float scl = (s == 0) ? 0.25f : 1.0f;   // fold q scale into weights
        const float* w0 = qkv_w + s * 96 + nc0;
        const float* w1 = qkv_w + s * 96 + nc1;
        uint4 r;
        r.x = packh(w0[(k0)     * 288] * scl, w0[(k0 + 1) * 288] * scl);
        r.y = packh(w0[(k0 + 8) * 288] * scl, w0[(k0 + 9) * 288] * scl);
        r.z = packh(w1[(k0)     * 288] * scl, w1[(k0 + 1) * 288] * scl);
        r.w = packh(w1[(k0 + 8) * 288] * scl, w1[(k0 + 9) * 288] * scl);
        g_qwf4[idx] = r;
    } else if (idx < 4608) {
        int j = idx - 3456;
        int lane = j & 31, np = (j >> 5) % 6, kt = j / 192;
        int k0 = kt * 16 + (lane & 3) * 2;
        int nc0 = (2 * np) * 8 + (lane >> 2);
        int nc1 = nc0 + 8;
        const float* w0 = proj_w + nc0;
        const float* w1 = proj_w + nc1;
        uint4 r;
        r.x = packh(w0[(k0)     * 96], w0[(k0 + 1) * 96]);
        r.y = packh(w0[(k0 + 8) * 96], w0[(k0 + 9) * 96]);
        r.z = packh(w1[(k0)     * 96], w1[(k0 + 1) * 96]);
        r.w = packh(w1[(k0 + 8) * 96], w1[(k0 + 9) * 96]);
        g_pwf4[j] = r;
    } else if (idx < 4608 + 6144) {
        int j = idx - 4608;
        int lane = j & 31, nt = (j >> 5) & 7, mt = (j >> 8) & 3, h = j >> 10;
        int r0 = mt * 16 + (lane >> 2);
        int c0 = nt * 8 + (lane & 3) * 2;
        float b00 = rpb[ridx[(r0)     * 64 + c0]     * HEADS + h];
        float b01 = rpb[ridx[(r0)     * 64 + c0 + 1] * HEADS + h];
        float b10 = rpb[ridx[(r0 + 8) * 64 + c0]     * HEADS + h];
        float b11 = rpb[ridx[(r0 + 8) * 64 + c0 + 1] * HEADS + h];
        uint2 r;
        r.x = packh(b00, b01);
        r.y = packh(b10, b11);
        g_biasf[j] = r;
    } else {
        int j = idx - (4608 + 6144);
        if (j < nW * 1024) {
            int lane = j & 31, nt = (j >> 5) & 7, mt = (j >> 8) & 3, w = j >> 10;
            int r0 = mt * 16 + (lane >> 2);
            int c0 = nt * 8 + (lane & 3) * 2;
            const float* mb = mask + (size_t)w * 4096;
            float2 a = *(const float2*)(mb + (size_t)r0 * 64 + c0);
            float2 c = *(const float2*)(mb + (size_t)(r0 + 8) * 64 + c0);
            uint2 r;
            r.x = packh(a.x, a.y);
            r.y = packh(c.x, c.y);
            g_maskf[j] = r;
        }
    }
}

// ---- PTX helpers ----
__device__ __forceinline__ uint32_t smem_u32(const void* p) {
    uint32_t a;
    asm("{ .reg .u64 t; cvta.to.shared.u64 t, %1; cvt.u32.u64 %0, t; }" : "=r"(a) : "l"(p));
    return a;
}
__device__ __forceinline__ void ldsm_x4(uint32_t* r, uint32_t a) {
    asm volatile("ldmatrix.sync.aligned.m8n8.x4.shared.b16 {%0,%1,%2,%3}, [%4];"
        : "=r"(r[0]), "=r"(r[1]), "=r"(r[2]), "=r"(r[3]) : "r"(a));
}
__device__ __forceinline__ void ldsm_x4t(uint32_t* r, uint32_t a) {
    asm volatile("ldmatrix.sync.aligned.m8n8.x4.trans.shared.b16 {%0,%1,%2,%3}, [%4];"
        : "=r"(r[0]), "=r"(r[1]), "=r"(r[2]), "=r"(r[3]) : "r"(a));
}
__device__ __forceinline__ void mma_h(float* c, const uint32_t* a,
                                      uint32_t b0, uint32_t b1) {
    asm volatile("mma.sync.aligned.m16n8k16.row.col.f32.f16.f16.f32 "
        "{%0,%1,%2,%3}, {%4,%5,%6,%7}, {%8,%9}, {%0,%1,%2,%3};"
        : "+f"(c[0]), "+f"(c[1]), "+f"(c[2]), "+f"(c[3])
        : "r"(a[0]), "r"(a[1]), "r"(a[2]), "r"(a[3]), "r"(b0), "r"(b1));
}

extern __shared__ char smc[];

__global__ void __launch_bounds__(THREADS, 2)
win_attn_mma(const float* __restrict__ x,
             const float* __restrict__ qkv_b,
             const float* __restrict__ proj_b,
             float* __restrict__ out,
             int nW)
{
    const int t = threadIdx.x, wid = t >> 5, lane = t & 31, b = blockIdx.x;
    const uint32_t sb = smem_u32(smc);
    const int mt = wid & 3;      // m tile 0..3
    const int g6 = wid >> 2;     // n group 0..1 -> heads 3*g6..3*g6+2

    // ---- load A fragments (x) from gmem, single fp16 ----
    uint32_t xah[6][4];
    {
        const float* xb = x + (size_t)b * 6144;
        const int gr = lane >> 2, ck = (lane & 3) * 2;
        const float* base = xb + (size_t)(mt * 16 + gr) * 96 + ck;
        #pragma unroll
        for (int kt = 0; kt < 6; kt++) {
            float2 v00 = *(const float2*)(base + kt * 16);
            float2 v10 = *(const float2*)(base + kt * 16 + 8 * 96);
            float2 v01 = *(const float2*)(base + kt * 16 + 8);
            float2 v11 = *(const float2*)(base + kt * 16 + 8 * 96 + 8);
            xah[kt][0] = packh(v00.x, v00.y);
            xah[kt][1] = packh(v10.x, v10.y);
            xah[kt][2] = packh(v01.x, v01.y);
            xah[kt][3] = packh(v11.x, v11.y);
        }
    }
    const int r0 = mt * 16 + (lane >> 2);

    // ---- q slice (s=0): accumulators stay in registers as A-fragments ----
    uint32_t qfrag[3][4];
    {
        float acc[6][4];
        #pragma unroll
        for (int j = 0; j < 6; j++)
            { acc[j][0] = 0.f; acc[j][1] = 0.f; acc[j][2] = 0.f; acc[j][3] = 0.f; }
        #pragma unroll
        for (int kt = 0; kt < 6; kt++) {
            #pragma unroll
            for (int jp = 0; jp < 3; jp++) {
                int fi = (kt * 6 + g6 * 3 + jp) * 32 + lane;
                uint4 w = g_qwf4[fi];
                mma_h(acc[2*jp],   xah[kt], w.x, w.y);
                mma_h(acc[2*jp+1], xah[kt], w.z, w.w);
            }
        }
        #pragma unroll
        for (int iu = 0; iu < 3; iu++) {
            int c0 = (g6 * 6 + 2 * iu) * 8 + (lane & 3) * 2;   // bias cols (weights pre-scaled)
            float b0 = __ldg(qkv_b + c0)     * 0.25f;
            float b1 = __ldg(qkv_b + c0 + 1) * 0.25f;
            float b2 = __ldg(qkv_b + c0 + 8) * 0.25f;
            float b3 = __ldg(qkv_b + c0 + 9) * 0.25f;
            qfrag[iu][0] = packh(acc[2*iu][0]   + b0, acc[2*iu][1]   + b1);
            qfrag[iu][1] = packh(acc[2*iu][2]   + b0, acc[2*iu][3]   + b1);
            qfrag[iu][2] = packh(acc[2*iu+1][0] + b2, acc[2*iu+1][1] + b3);
            qfrag[iu][3] = packh(acc[2*iu+1][2] + b2, acc[2*iu+1][3] + b3);
        }
    }

    // ---- k,v slices (s=1,2): store to smem planes ----
    #pragma unroll 1
    for (int s = 1; s < 3; s++) {
        float acc[6][4];
        #pragma unroll
        for (int j = 0; j < 6; j++)
            { acc[j][0] = 0.f; acc[j][1] = 0.f; acc[j][2] = 0.f; acc[j][3] = 0.f; }
        #pragma unroll
        for (int kt = 0; kt < 6; kt++) {
            #pragma unroll
            for (int jp = 0; jp < 3; jp++) {
                int fi = ((s * 6 + kt) * 6 + g6 * 3 + jp) * 32 + lane;
                uint4 w = g_qwf4[fi];
                mma_h(acc[2*jp],   xah[kt], w.x, w.y);
                mma_h(acc[2*jp+1], xah[kt], w.z, w.w);
            }
        }
        const uint32_t pofs = (s == 1) ? KP_OFF : VP_OFF;
        #pragma unroll
        for (int j = 0; j < 6; j++) {
            int c0 = (g6 * 6 + j) * 8 + (lane & 3) * 2;
            float b0 = __ldg(qkv_b + s * 96 + c0), b1 = __ldg(qkv_b + s * 96 + c0 + 1);
            uint32_t off = (uint32_t)r0 * PITCHB + c0 * 2;
            *(uint32_t*)(smc + pofs + off) = packh(acc[j][0] + b0, acc[j][1] + b1);
            *(uint32_t*)(smc + pofs + off + 8 * PITCHB) = packh(acc[j][2] + b0, acc[j][3] + b1);
        }
    }
    __syncthreads();   // k/v complete

    // ---- preload mask fragments (h-independent, reused across 3 units) ----
    uint2 mreg[8];
    {
        const uint2* mfp = g_maskf + ((size_t)(b % nW) * 4 + mt) * 256 + lane;
        #pragma unroll
        for (int nt = 0; nt < 8; nt++) mreg[nt] = mfp[nt * 32];
    }

    // ---- attention: warp handles heads 3*g6 + {0,1,2} on its mt tile ----
    uint32_t oah[3][4];              // own O tiles in proj-A fragment form
    #pragma unroll 1
    for (int iu = 0; iu < 3; iu++) {
        const int h = 3 * g6 + iu;

        float s8[8][4];
        #pragma unroll
        for (int ntp = 0; ntp < 4; ntp++) {
            uint32_t kh[4];
            uint32_t br = (uint32_t)(ntp * 16 + (lane & 15)) * PITCHB
                        + (uint32_t)(h * 16 + ((lane >> 4) << 3)) * 2;
            ldsm_x4(kh, sb + KP_OFF + br);
            #pragma unroll
            for (int half = 0; half < 2; half++) {
                int nt = 2 * ntp + half;
                s8[nt][0] = 0.f; s8[nt][1] = 0.f; s8[nt][2] = 0.f; s8[nt][3] = 0.f;
                mma_h(s8[nt], qfrag[iu], kh[half], kh[half + 2]);
            }
        }
        // + (bias + mask), both fragment-ordered; exp WITHOUT max-shift (|S| << 88)
        float sum0 = 0.f, sum1 = 0.f;
        {
            const uint2* bfp = g_biasf + ((size_t)h * 4 + mt) * 256 + lane;
            #pragma unroll
            for (int nt = 0; nt < 8; nt++) {
                uint2 bw = bfp[nt * 32];
                __half2 a0 = __hadd2(*reinterpret_cast<__half2*>(&bw.x),
                                     *reinterpret_cast<__half2*>(&mreg[nt].x));
                __half2 a1 = __hadd2(*reinterpret_cast<__half2*>(&bw.y),
                                     *reinterpret_cast<__half2*>(&mreg[nt].y));
                float2 f0 = __half22float2(a0);
                float2 f1 = __half22float2(a1);
                s8[nt][0] = __expf(s8[nt][0] + f0.x); sum0 += s8[nt][0];
                s8[nt][1] = __expf(s8[nt][1] + f0.y); sum0 += s8[nt][1];
                s8[nt][2] = __expf(s8[nt][2] + f1.x); sum1 += s8[nt][2];
                s8[nt][3] = __expf(s8[nt][3] + f1.y); sum1 += s8[nt][3];
            }
        }
        sum0 += __shfl_xor_sync(0xffffffffu, sum0, 1);
        sum0 += __shfl_xor_sync(0xffffffffu, sum0, 2);
        sum1 += __shfl_xor_sync(0xffffffffu, sum1, 1);
        sum1 += __shfl_xor_sync(0xffffffffu, sum1, 2);
        float inv0 = 1.f / sum0, inv1 = 1.f / sum1;
        #pragma unroll
        for (int nt = 0; nt < 8; nt++) {
            s8[nt][0] *= inv0; s8[nt][1] *= inv0;
            s8[nt][2] *= inv1; s8[nt][3] *= inv1;
        }
        // PV: O(16x16) = P(16x64) @ V(64x16); P,V single fp16
        float o[2][4];
        o[0][0]=0.f;o[0][1]=0.f;o[0][2]=0.f;o[0][3]=0.f;
        o[1][0]=0.f;o[1][1]=0.f;o[1][2]=0.f;o[1][3]=0.f;
        #pragma unroll
        for (int kt = 0; kt < 4; kt++) {
            uint32_t pa[4];
            pa[0] = packh(s8[2*kt][0],   s8[2*kt][1]);
            pa[1] = packh(s8[2*kt][2],   s8[2*kt][3]);
            pa[2] = packh(s8[2*kt+1][0], s8[2*kt+1][1]);
            pa[3] = packh(s8[2*kt+1][2], s8[2*kt+1][3]);
            uint32_t vr = (uint32_t)(kt * 16 + (lane & 15)) * PITCHB
                        + (uint32_t)(h * 16 + ((lane >> 4) << 3)) * 2;
            uint32_t vh[4];
            ldsm_x4t(vh, sb + VP_OFF + vr);
            mma_h(o[0], pa, vh[0], vh[1]);
            mma_h(o[1], pa, vh[2], vh[3]);
        }
        // O single fp16: keep in regs AND store into O plane for partner warps
        #pragma unroll
        for (int nt2 = 0; nt2 < 2; nt2++) {
            int c0 = h * 16 + nt2 * 8 + (lane & 3) * 2;
            uint32_t p0 = packh(o[nt2][0], o[nt2][1]);
            uint32_t p1 = packh(o[nt2][2], o[nt2][3]);
            oah[iu][nt2*2]   = p0;
            oah[iu][nt2*2+1] = p1;
            uint32_t off = (uint32_t)r0 * PITCHB + c0 * 2;
            *(uint32_t*)(smc + OP_OFF + off)              = p0;
            *(uint32_t*)(smc + OP_OFF + off + 8 * PITCHB) = p1;
        }
    }
    __syncthreads();   // O complete

    // ---- proj GEMM: A = O single fp16 (own tiles: kt in [3*g6, 3*g6+2]) ----
    {
        float acc[6][4];
        #pragma unroll
        for (int j = 0; j < 6; j++)
            { acc[j][0] = 0.f; acc[j][1] = 0.f; acc[j][2] = 0.f; acc[j][3] = 0.f; }
        #pragma unroll
        for (int kt = 0; kt < 6; kt++) {
            uint32_t ah[4];
            if (kt / 3 == g6) {
                int iu = kt - 3 * g6;
                ah[0] = oah[iu][0]; ah[1] = oah[iu][1]; ah[2] = oah[iu][2]; ah[3] = oah[iu][3];
            } else {
                uint32_t ar = (uint32_t)(mt * 16 + (lane & 15)) * PITCHB
                            + (uint32_t)(kt * 16 + ((lane >> 4) << 3)) * 2;
                ldsm_x4(ah, sb + OP_OFF + ar);
            }
            #pragma unroll
            for (int jp = 0; jp < 3; jp++) {
                int fi = (kt * 6 + g6 * 3 + jp) * 32 + lane;
                uint4 w = g_pwf4[fi];
                mma_h(acc[2*jp],   ah, w.x, w.y);
                mma_h(acc[2*jp+1], ah, w.z, w.w);
            }
        }
        float* ob = out + (size_t)b * 6144;
        #pragma unroll
        for (int j = 0; j < 6; j++) {
            int c0 = (g6 * 6 + j) * 8 + (lane & 3) * 2;
            float b0 = __ldg(proj_b + c0), b1 = __ldg(proj_b + c0 + 1);
            *(float2*)(ob + (size_t)r0 * 96 + c0) =
                make_float2(acc[j][0] + b0, acc[j][1] + b1);
            *(float2*)(ob + (size_t)(r0 + 8) * 96 + c0) =
                make_float2(acc[j][2] + b0, acc[j][3] + b1);
        }
    }
}

extern "C" void kernel_launch(void* const* d_in, const int* in_sizes, int n_in,
                              void* d_out, int out_size) {
    const float* x      = (const float*)d_in[0];
    const float* mask   = (const float*)d_in[1];
    const float* qkv_w  = (const float*)d_in[2];
    const float* qkv_b  = (const float*)d_in[3];
    const float* proj_w = (const float*)d_in[4];
    const float* proj_b = (const float*)d_in[5];
    const float* rpb    = (const float*)d_in[6];
    const int*   ridx   = (const int*)d_in[7];
    float* out = (float*)d_out;

    const int B_ = in_sizes[0] / (N_TOK * DIM);        // 8192
    const int nW = in_sizes[1] / (N_TOK * N_TOK);      // 512

    int prep_total = 4608 + 6144 + nW * 1024;
    prep_kernel<<<(prep_total + 255) / 256, 256>>>(qkv_w, proj_w, rpb, ridx,
                                                   mask, nW);

    cudaFuncSetAttribute(win_attn_mma,
                         cudaFuncAttributeMaxDynamicSharedMemorySize, SMEM_BYTES);
    win_attn_mma<<<B_, THREADS, SMEM_BYTES>>>(x, qkv_b, proj_b, out, nW);
}

// round 15
// speedup vs baseline: 1.5716x; 1.0865x over previous
#include <cuda_runtime.h>
#include <cuda_fp16.h>
#include <cstdint>

#define THREADS 256
#define N_TOK   64
#define DIM     96
#define HEADS   6

#define PITCHB  208u    // bytes per smem row (104 fp16; 13*16B, conflict-free LDSM)

// ---- smem planes: X/O (shared), K, V (single fp16 each) ----
#define XP_OFF   0u          // x staging, later O-exchange
#define KP_OFF   13312u      // k plane; later fp32 out staging (with V: 64x104 f32)
#define VP_OFF   26624u
#define SMEM_BYTES 39936u    // 2 CTAs/SM

// ---- prepped globals (all in mma-fragment order) ----
__device__ uint4 g_qwf4[3456];            // qkv W: 3 slices * 6 kt * 6 np * 32 lanes (q pre-scaled 0.25)
__device__ uint4 g_pwf4[1152];            // proj W: 6 kt * 6 np * 32 lanes
__device__ uint2 g_biasf[HEADS * 4 * 8 * 32];   // [(h*4+mt)*8+nt][lane]
__device__ uint2 g_maskf[512 * 4 * 8 * 32];     // [(w*4+mt)*8+nt][lane]

__device__ __forceinline__ uint32_t packh(float a, float b) {
    __half2 v;
    v.x = __float2half_rn(a);
    v.y = __float2half_rn(b);
    return *reinterpret_cast<uint32_t*>(&v);
}

__global__ void __launch_bounds__(256)
prep_kernel(const float* __restrict__ qkv_w, const float* __restrict__ proj_w,
            const float* __restrict__ rpb, const int* __restrict__ ridx,
            const float* __restrict__ mask, int nW)
{
    int idx = blockIdx.x * 256 + threadIdx.x;
    if (idx < 3456) {
        int lane = idx & 31, np = (idx >> 5) % 6, kt = (idx / 192) % 6, s = idx / 1152;
        int k0 = kt * 16 + (lane & 3) * 2;
        int nc0 = (2 * np) * 8 + (lane >> 2);
        int nc1 = nc0 + 8;
        const float scl = (s == 0) ? 0.25f : 1.0f;   // fold q scale into weights
        const float* w0 = qkv_w + s * 96 + nc0;
        const float* w1 = qkv_w + s * 96 + nc1;
        uint4 r;
        r.x = packh(w0[(k0)     * 288] * scl, w0[(k0 + 1) * 288] * scl);
        r.y = packh(w0[(k0 + 8) * 288] * scl, w0[(k0 + 9) * 288] * scl);
        r.z = packh(w1[(k0)     * 288] * scl, w1[(k0 + 1) * 288] * scl);
        r.w = packh(w1[(k0 + 8) * 288] * scl, w1[(k0 + 9) * 288] * scl);
        g_qwf4[idx] = r;
    } else if (idx < 4608) {
        int j = idx - 3456;
        int lane = j & 31, np = (j >> 5) % 6, kt = j / 192;
        int k0 = kt * 16 + (lane & 3) * 2;
        int nc0 = (2 * np) * 8 + (lane >> 2);
        int nc1 = nc0 + 8;
        const float* w0 = proj_w + nc0;
        const float* w1 = proj_w + nc1;
        uint4 r;
        r.x = packh(w0[(k0)     * 96], w0[(k0 + 1) * 96]);
        r.y = packh(w0[(k0 + 8) * 96], w0[(k0 + 9) * 96]);
        r.z = packh(w1[(k0)     * 96], w1[(k0 + 1) * 96]);
        r.w = packh(w1[(k0 + 8) * 96], w1[(k0 + 9) * 96]);
        g_pwf4[j] = r;
    } else if (idx < 4608 + 6144) {
        int j = idx - 4608;
        int lane = j & 31, nt = (j >> 5) & 7, mt = (j >> 8) & 3, h = j >> 10;
        int r0 = mt * 16 + (lane >> 2);
        int c0 = nt * 8 + (lane & 3) * 2;
        float b00 = rpb[ridx[(r0)     * 64 + c0]     * HEADS + h];
        float b01 = rpb[ridx[(r0)     * 64 + c0 + 1] * HEADS + h];
        float b10 = rpb[ridx[(r0 + 8) * 64 + c0]     * HEADS + h];
        float b11 = rpb[ridx[(r0 + 8) * 64 + c0 + 1] * HEADS + h];
        uint2 r;
        r.x = packh(b00, b01);
        r.y = packh(b10, b11);
        g_biasf[j] = r;
    } else {
        int j = idx - (4608 + 6144);
        if (j < nW * 1024) {
            int lane = j & 31, nt = (j >> 5) & 7, mt = (j >> 8) & 3, w = j >> 10;
            int r0 = mt * 16 + (lane >> 2);
            int c0 = nt * 8 + (lane & 3) * 2;
            const float* mb = mask + (size_t)w * 4096;
            float2 a = *(const float2*)(mb + (size_t)r0 * 64 + c0);
            float2 c = *(const float2*)(mb + (size_t)(r0 + 8) * 64 + c0);
            uint2 r;
            r.x = packh(a.x, a.y);
            r.y = packh(c.x, c.y);
            g_maskf[j] = r;
        }
    }
}

// ---- PTX helpers ----
__device__ __forceinline__ uint32_t smem_u32(const void* p) {
    uint32_t a;
    asm("{ .reg .u64 t; cvta.to.shared.u64 t, %1; cvt.u32.u64 %0, t; }" : "=r"(a) : "l"(p));
    return a;
}
__device__ __forceinline__ void ldsm_x4(uint32_t* r, uint32_t a) {
    asm volatile("ldmatrix.sync.aligned.m8n8.x4.shared.b16 {%0,%1,%2,%3}, [%4];"
        : "=r"(r[0]), "=r"(r[1]), "=r"(r[2]), "=r"(r[3]) : "r"(a));
}
__device__ __forceinline__ void ldsm_x4t(uint32_t* r, uint32_t a) {
    asm volatile("ldmatrix.sync.aligned.m8n8.x4.trans.shared.b16 {%0,%1,%2,%3}, [%4];"
        : "=r"(r[0]), "=r"(r[1]), "=r"(r[2]), "=r"(r[3]) : "r"(a));
}
__device__ __forceinline__ void mma_h(float* c, const uint32_t* a,
                                      uint32_t b0, uint32_t b1) {
    asm volatile("mma.sync.aligned.m16n8k16.row.col.f32.f16.f16.f32 "
        "{%0,%1,%2,%3}, {%4,%5,%6,%7}, {%8,%9}, {%0,%1,%2,%3};"
        : "+f"(c[0]), "+f"(c[1]), "+f"(c[2]), "+f"(c[3])
        : "r"(a[0]), "r"(a[1]), "r"(a[2]), "r"(a[3]), "r"(b0), "r"(b1));
}

extern __shared__ char smc[];

__global__ void __launch_bounds__(THREADS, 2)
win_attn_mma(const float* __restrict__ x,
             const float* __restrict__ qkv_b,
             const float* __restrict__ proj_b,
             float* __restrict__ out,
             int nW)
{
    const int t = threadIdx.x, wid = t >> 5, lane = t & 31, b = blockIdx.x;
    const uint32_t sb = smem_u32(smc);
    const int mt = wid & 3;      // m tile 0..3
    const int g6 = wid >> 2;     // n group 0..1 -> heads 3*g6..3*g6+2

    // ---- stage x: coalesced LDG.128 -> packed fp16 X plane ----
    {
        const float4* xb4 = (const float4*)(x + (size_t)b * 6144);
        #pragma unroll
        for (int i = 0; i < 6; i++) {
            int e4 = t + i * THREADS;            // 1536 float4
            int row = e4 / 24, c4 = e4 % 24;
            float4 v = xb4[e4];
            uint2 p;
            p.x = packh(v.x, v.y);
            p.y = packh(v.z, v.w);
            *(uint2*)(smc + XP_OFF + (uint32_t)row * PITCHB + c4 * 8) = p;
        }
    }
    __syncthreads();

    // ---- load A fragments from X plane (conflict-free ldsm) ----
    uint32_t xah[6][4];
    #pragma unroll
    for (int kt = 0; kt < 6; kt++) {
        uint32_t ar = (uint32_t)(mt * 16 + (lane & 15)) * PITCHB
                    + (uint32_t)(kt * 16 + ((lane >> 4) << 3)) * 2;
        ldsm_x4(xah[kt], sb + XP_OFF + ar);
    }
    const int r0 = mt * 16 + (lane >> 2);

    // ---- q slice (s=0): accumulators stay in registers as A-fragments ----
    uint32_t qfrag[3][4];
    {
        float acc[6][4];
        #pragma unroll
        for (int j = 0; j < 6; j++)
            { acc[j][0] = 0.f; acc[j][1] = 0.f; acc[j][2] = 0.f; acc[j][3] = 0.f; }
        #pragma unroll
        for (int kt = 0; kt < 6; kt++) {
            #pragma unroll
            for (int jp = 0; jp < 3; jp++) {
                int fi = (kt * 6 + g6 * 3 + jp) * 32 + lane;
                uint4 w = g_qwf4[fi];
                mma_h(acc[2*jp],   xah[kt], w.x, w.y);
                mma_h(acc[2*jp+1], xah[kt], w.z, w.w);
            }
        }
        #pragma unroll
        for (int iu = 0; iu < 3; iu++) {
            int c0 = (g6 * 6 + 2 * iu) * 8 + (lane & 3) * 2;
            float b0 = __ldg(qkv_b + c0)     * 0.25f;
            float b1 = __ldg(qkv_b + c0 + 1) * 0.25f;
            float b2 = __ldg(qkv_b + c0 + 8) * 0.25f;
            float b3 = __ldg(qkv_b + c0 + 9) * 0.25f;
            qfrag[iu][0] = packh(acc[2*iu][0]   + b0, acc[2*iu][1]   + b1);
            qfrag[iu][1] = packh(acc[2*iu][2]   + b0, acc[2*iu][3]   + b1);
            qfrag[iu][2] = packh(acc[2*iu+1][0] + b2, acc[2*iu+1][1] + b3);
            qfrag[iu][3] = packh(acc[2*iu+1][2] + b2, acc[2*iu+1][3] + b3);
        }
    }

    // ---- k,v slices (s=1,2): store to smem planes ----
    #pragma unroll 1
    for (int s = 1; s < 3; s++) {
        float acc[6][4];
        #pragma unroll
        for (int j = 0; j < 6; j++)
            { acc[j][0] = 0.f; acc[j][1] = 0.f; acc[j][2] = 0.f; acc[j][3] = 0.f; }
        #pragma unroll
        for (int kt = 0; kt < 6; kt++) {
            #pragma unroll
            for (int jp = 0; jp < 3; jp++) {
                int fi = ((s * 6 + kt) * 6 + g6 * 3 + jp) * 32 + lane;
                uint4 w = g_qwf4[fi];
                mma_h(acc[2*jp],   xah[kt], w.x, w.y);
                mma_h(acc[2*jp+1], xah[kt], w.z, w.w);
            }
        }
        const uint32_t pofs = (s == 1) ? KP_OFF : VP_OFF;
        #pragma unroll
        for (int j = 0; j < 6; j++) {
            int c0 = (g6 * 6 + j) * 8 + (lane & 3) * 2;
            float b0 = __ldg(qkv_b + s * 96 + c0), b1 = __ldg(qkv_b + s * 96 + c0 + 1);
            uint32_t off = (uint32_t)r0 * PITCHB + c0 * 2;
            *(uint32_t*)(smc + pofs + off) = packh(acc[j][0] + b0, acc[j][1] + b1);
            *(uint32_t*)(smc + pofs + off + 8 * PITCHB) = packh(acc[j][2] + b0, acc[j][3] + b1);
        }
    }
    __syncthreads();   // k/v complete; X reads done (O may overwrite plane 0)

    // ---- preload mask fragments (h-independent, reused across 3 units) ----
    uint2 mreg[8];
    {
        const uint2* mfp = g_maskf + ((size_t)(b % nW) * 4 + mt) * 256 + lane;
        #pragma unroll
        for (int nt = 0; nt < 8; nt++) mreg[nt] = mfp[nt * 32];
    }

    // ---- attention: warp handles heads 3*g6 + {0,1,2} on its mt tile ----
    uint32_t oah[3][4];              // own O tiles in proj-A fragment form
    #pragma unroll 1
    for (int iu = 0; iu < 3; iu++) {
        const int h = 3 * g6 + iu;

        float s8[8][4];
        #pragma unroll
        for (int ntp = 0; ntp < 4; ntp++) {
            uint32_t kh[4];
            uint32_t br = (uint32_t)(ntp * 16 + (lane & 15)) * PITCHB
                        + (uint32_t)(h * 16 + ((lane >> 4) << 3)) * 2;
            ldsm_x4(kh, sb + KP_OFF + br);
            #pragma unroll
            for (int half = 0; half < 2; half++) {
                int nt = 2 * ntp + half;
                s8[nt][0] = 0.f; s8[nt][1] = 0.f; s8[nt][2] = 0.f; s8[nt][3] = 0.f;
                mma_h(s8[nt], qfrag[iu], kh[half], kh[half + 2]);
            }
        }
        // + (bias + mask); exp WITHOUT max-shift (|S| << 88)
        float sum0 = 0.f, sum1 = 0.f;
        {
            const uint2* bfp = g_biasf + ((size_t)h * 4 + mt) * 256 + lane;
            #pragma unroll
            for (int nt = 0; nt < 8; nt++) {
                uint2 bw = bfp[nt * 32];
                __half2 a0 = __hadd2(*reinterpret_cast<__half2*>(&bw.x),
                                     *reinterpret_cast<__half2*>(&mreg[nt].x));
                __half2 a1 = __hadd2(*reinterpret_cast<__half2*>(&bw.y),
                                     *reinterpret_cast<__half2*>(&mreg[nt].y));
                float2 f0 = __half22float2(a0);
                float2 f1 = __half22float2(a1);
                s8[nt][0] = __expf(s8[nt][0] + f0.x); sum0 += s8[nt][0];
                s8[nt][1] = __expf(s8[nt][1] + f0.y); sum0 += s8[nt][1];
                s8[nt][2] = __expf(s8[nt][2] + f1.x); sum1 += s8[nt][2];
                s8[nt][3] = __expf(s8[nt][3] + f1.y); sum1 += s8[nt][3];
            }
        }
        sum0 += __shfl_xor_sync(0xffffffffu, sum0, 1);
        sum0 += __shfl_xor_sync(0xffffffffu, sum0, 2);
        sum1 += __shfl_xor_sync(0xffffffffu, sum1, 1);
        sum1 += __shfl_xor_sync(0xffffffffu, sum1, 2);
        float inv0 = 1.f / sum0, inv1 = 1.f / sum1;
        #pragma unroll
        for (int nt = 0; nt < 8; nt++) {
            s8[nt][0] *= inv0; s8[nt][1] *= inv0;
            s8[nt][2] *= inv1; s8[nt][3] *= inv1;
        }
        // PV: O(16x16) = P(16x64) @ V(64x16); P,V single fp16
        float o[2][4];
        o[0][0]=0.f;o[0][1]=0.f;o[0][2]=0.f;o[0][3]=0.f;
        o[1][0]=0.f;o[1][1]=0.f;o[1][2]=0.f;o[1][3]=0.f;
        #pragma unroll
        for (int kt = 0; kt < 4; kt++) {
            uint32_t pa[4];
            pa[0] = packh(s8[2*kt][0],   s8[2*kt][1]);
            pa[1] = packh(s8[2*kt][2],   s8[2*kt][3]);
            pa[2] = packh(s8[2*kt+1][0], s8[2*kt+1][1]);
            pa[3] = packh(s8[2*kt+1][2], s8[2*kt+1][3]);
            uint32_t vr = (uint32_t)(kt * 16 + (lane & 15)) * PITCHB
                        + (uint32_t)(h * 16 + ((lane >> 4) << 3)) * 2;
            uint32_t vh[4];
            ldsm_x4t(vh, sb + VP_OFF + vr);
            mma_h(o[0], pa, vh[0], vh[1]);
            mma_h(o[1], pa, vh[2], vh[3]);
        }
        // O single fp16: keep in regs AND store into O plane for partner warps
        #pragma unroll
        for (int nt2 = 0; nt2 < 2; nt2++) {
            int c0 = h * 16 + nt2 * 8 + (lane & 3) * 2;
            uint32_t p0 = packh(o[nt2][0], o[nt2][1]);
            uint32_t p1 = packh(o[nt2][2], o[nt2][3]);
            oah[iu][nt2*2]   = p0;
            oah[iu][nt2*2+1] = p1;
            uint32_t off = (uint32_t)r0 * PITCHB + c0 * 2;
            *(uint32_t*)(smc + XP_OFF + off)              = p0;
            *(uint32_t*)(smc + XP_OFF + off + 8 * PITCHB) = p1;
        }
    }
    __syncthreads();   // O complete; K/V planes now dead

    // ---- proj GEMM: A = O single fp16 (own tiles: kt in [3*g6, 3*g6+2]) ----
    {
        float acc[6][4];
        #pragma unroll
        for (int j = 0; j < 6; j++)
            { acc[j][0] = 0.f; acc[j][1] = 0.f; acc[j][2] = 0.f; acc[j][3] = 0.f; }
        #pragma unroll
        for (int kt = 0; kt < 6; kt++) {
            uint32_t ah[4];
            if (kt / 3 == g6) {
                int iu = kt - 3 * g6;
                ah[0] = oah[iu][0]; ah[1] = oah[iu][1]; ah[2] = oah[iu][2]; ah[3] = oah[iu][3];
            } else {
                uint32_t ar = (uint32_t)(mt * 16 + (lane & 15)) * PITCHB
                            + (uint32_t)(kt * 16 + ((lane >> 4) << 3)) * 2;
                ldsm_x4(ah, sb + XP_OFF + ar);
            }
            #pragma unroll
            for (int jp = 0; jp < 3; jp++) {
                int fi = (kt * 6 + g6 * 3 + jp) * 32 + lane;
                uint4 w = g_pwf4[fi];
                mma_h(acc[2*jp],   ah, w.x, w.y);
                mma_h(acc[2*jp+1], ah, w.z, w.w);
            }
        }
        // stage fp32 results (+bias) into dead K/V region (pitch 104 floats, 8-bank offset)
        float* stg = (float*)(smc + KP_OFF);
        #pragma unroll
        for (int j = 0; j < 6; j++) {
            int c0 = (g6 * 6 + j) * 8 + (lane & 3) * 2;
            float b0 = __ldg(proj_b + c0), b1 = __ldg(proj_b + c0 + 1);
            *(float2*)(stg + (uint32_t)r0 * 104 + c0) =
                make_float2(acc[j][0] + b0, acc[j][1] + b1);
            *(float2*)(stg + (uint32_t)(r0 + 8) * 104 + c0) =
                make_float2(acc[j][2] + b0, acc[j][3] + b1);
        }
    }
    __syncthreads();

    // ---- coalesced output copy ----
    {
        const float* stg = (const float*)(smc + KP_OFF);
        float4* ob4 = (float4*)(out + (size_t)b * 6144);
        #pragma unroll
        for (int i = 0; i < 6; i++) {
            int e4 = t + i * THREADS;            // 1536 float4
            int row = e4 / 24, c4 = e4 % 24;
            ob4[e4] = *(const float4*)(stg + (uint32_t)row * 104 + c4 * 4);
        }
    }
}

extern "C" void kernel_launch(void* const* d_in, const int* in_sizes, int n_in,
                              void* d_out, int out_size) {
    const float* x      = (const float*)d_in[0];
    const float* mask   = (const float*)d_in[1];
    const float* qkv_w  = (const float*)d_in[2];
    const float* qkv_b  = (const float*)d_in[3];
    const float* proj_w = (const float*)d_in[4];
    const float* proj_b = (const float*)d_in[5];
    const float* rpb    = (const float*)d_in[6];
    const int*   ridx   = (const int*)d_in[7];
    float* out = (float*)d_out;

    const int B_ = in_sizes[0] / (N_TOK * DIM);        // 8192
    const int nW = in_sizes[1] / (N_TOK * N_TOK);      // 512

    int prep_total = 4608 + 6144 + nW * 1024;
    prep_kernel<<<(prep_total + 255) / 256, 256>>>(qkv_w, proj_w, rpb, ridx,
                                                   mask, nW);

    cudaFuncSetAttribute(win_attn_mma,
                         cudaFuncAttributeMaxDynamicSharedMemorySize, SMEM_BYTES);
    win_attn_mma<<<B_, THREADS, SMEM_BYTES>>>(x, qkv_b, proj_b, out, nW);
}

// round 16
// speedup vs baseline: 1.6258x; 1.0345x over previous
#include <cuda_runtime.h>
#include <cuda_fp16.h>
#include <cstdint>

#define THREADS 256
#define N_TOK   64
#define DIM     96
#define HEADS   6

#define PITCHB  208u    // bytes per smem row (104 fp16; 13*16B, conflict-free LDSM)
#define LOG2E   1.44269504088896f

// ---- smem planes: X/O (shared), K, V (single fp16 each) ----
#define XP_OFF   0u          // x staging, later O-exchange
#define KP_OFF   13312u      // k plane; later fp32 out staging
#define VP_OFF   26624u
#define SMEM_BYTES 39936u    // 2 CTAs/SM

// ---- prepped globals (all in mma-fragment order) ----
// q weights pre-scaled by 0.25*log2e; bias/mask tables pre-scaled by log2e.
__device__ uint4 g_qwf4[3456];            // qkv W: 3 slices * 6 kt * 6 np * 32 lanes
__device__ uint4 g_pwf4[1152];            // proj W: 6 kt * 6 np * 32 lanes
__device__ uint2 g_biasf[HEADS * 4 * 8 * 32];   // [(h*4+mt)*8+nt][lane]
__device__ uint2 g_maskf[512 * 4 * 8 * 32];     // [(w*4+mt)*8+nt][lane]

__device__ __forceinline__ uint32_t packh(float a, float b) {
    __half2 v = __floats2half2_rn(a, b);   // single cvt.rn.f16x2.f32
    return *reinterpret_cast<uint32_t*>(&v);
}
__device__ __forceinline__ float ex2f(float v) {
    float r;
    asm("ex2.approx.f32 %0, %1;" : "=f"(r) : "f"(v));
    return r;
}

__global__ void __launch_bounds__(256)
prep_kernel(const float* __restrict__ qkv_w, const float* __restrict__ proj_w,
            const float* __restrict__ rpb, const int* __restrict__ ridx,
            const float* __restrict__ mask, int nW)
{
    int idx = blockIdx.x * 256 + threadIdx.x;
    if (idx < 3456) {
        int lane = idx & 31, np = (idx >> 5) % 6, kt = (idx / 192) % 6, s = idx / 1152;
        int k0 = kt * 16 + (lane & 3) * 2;
        int nc0 = (2 * np) * 8 + (lane >> 2);
        int nc1 = nc0 + 8;
        const float scl = (s == 0) ? 0.25f * LOG2E : 1.0f;  // fold q scale + log2e
        const float* w0 = qkv_w + s * 96 + nc0;
        const float* w1 = qkv_w + s * 96 + nc1;
        uint4 r;
        r.x = packh(w0[(k0)     * 288] * scl, w0[(k0 + 1) * 288] * scl);
        r.y = packh(w0[(k0 + 8) * 288] * scl, w0[(k0 + 9) * 288] * scl);
        r.z = packh(w1[(k0)     * 288] * scl, w1[(k0 + 1) * 288] * scl);
        r.w = packh(w1[(k0 + 8) * 288] * scl, w1[(k0 + 9) * 288] * scl);
        g_qwf4[idx] = r;
    } else if (idx < 4608) {
        int j = idx - 3456;
        int lane = j & 31, np = (j >> 5) % 6, kt = j / 192;
        int k0 = kt * 16 + (lane & 3) * 2;
        int nc0 = (2 * np) * 8 + (lane >> 2);
        int nc1 = nc0 + 8;
        const float* w0 = proj_w + nc0;
        const float* w1 = proj_w + nc1;
        uint4 r;
        r.x = packh(w0[(k0)     * 96], w0[(k0 + 1) * 96]);
        r.y = packh(w0[(k0 + 8) * 96], w0[(k0 + 9) * 96]);
        r.z = packh(w1[(k0)     * 96], w1[(k0 + 1) * 96]);
        r.w = packh(w1[(k0 + 8) * 96], w1[(k0 + 9) * 96]);
        g_pwf4[j] = r;
    } else if (idx < 4608 + 6144) {
        int j = idx - 4608;
        int lane = j & 31, nt = (j >> 5) & 7, mt = (j >> 8) & 3, h = j >> 10;
        int r0 = mt * 16 + (lane >> 2);
        int c0 = nt * 8 + (lane & 3) * 2;
        float b00 = rpb[ridx[(r0)     * 64 + c0]     * HEADS + h] * LOG2E;
        float b01 = rpb[ridx[(r0)     * 64 + c0 + 1] * HEADS + h] * LOG2E;
        float b10 = rpb[ridx[(r0 + 8) * 64 + c0]     * HEADS + h] * LOG2E;
        float b11 = rpb[ridx[(r0 + 8) * 64 + c0 + 1] * HEADS + h] * LOG2E;
        uint2 r;
        r.x = packh(b00, b01);
        r.y = packh(b10, b11);
        g_biasf[j] = r;
    } else {
        int j = idx - (4608 + 6144);
        if (j < nW * 1024) {
            int lane = j & 31, nt = (j >> 5) & 7, mt = (j >> 8) & 3, w = j >> 10;
            int r0 = mt * 16 + (lane >> 2);
            int c0 = nt * 8 + (lane & 3) * 2;
            const float* mb = mask + (size_t)w * 4096;
            float2 a = *(const float2*)(mb + (size_t)r0 * 64 + c0);
            float2 c = *(const float2*)(mb + (size_t)(r0 + 8) * 64 + c0);
            uint2 r;
            r.x = packh(a.x * LOG2E, a.y * LOG2E);
            r.y = packh(c.x * LOG2E, c.y * LOG2E);
            g_maskf[j] = r;
        }
    }
}

// ---- PTX helpers ----
__device__ __forceinline__ uint32_t smem_u32(const void* p) {
    uint32_t a;
    asm("{ .reg .u64 t; cvta.to.shared.u64 t, %1; cvt.u32.u64 %0, t; }" : "=r"(a) : "l"(p));
    return a;
}
__device__ __forceinline__ void ldsm_x4(uint32_t* r, uint32_t a) {
    asm volatile("ldmatrix.sync.aligned.m8n8.x4.shared.b16 {%0,%1,%2,%3}, [%4];"
        : "=r"(r[0]), "=r"(r[1]), "=r"(r[2]), "=r"(r[3]) : "r"(a));
}
__device__ __forceinline__ void ldsm_x4t(uint32_t* r, uint32_t a) {
    asm volatile("ldmatrix.sync.aligned.m8n8.x4.trans.shared.b16 {%0,%1,%2,%3}, [%4];"
        : "=r"(r[0]), "=r"(r[1]), "=r"(r[2]), "=r"(r[3]) : "r"(a));
}
__device__ __forceinline__ void mma_h(float* c, const uint32_t* a,
                                      uint32_t b0, uint32_t b1) {
    asm volatile("mma.sync.aligned.m16n8k16.row.col.f32.f16.f16.f32 "
        "{%0,%1,%2,%3}, {%4,%5,%6,%7}, {%8,%9}, {%0,%1,%2,%3};"
        : "+f"(c[0]), "+f"(c[1]), "+f"(c[2]), "+f"(c[3])
        : "r"(a[0]), "r"(a[1]), "r"(a[2]), "r"(a[3]), "r"(b0), "r"(b1));
}

extern __shared__ char smc[];

__global__ void __launch_bounds__(THREADS, 2)
win_attn_mma(const float* __restrict__ x,
             const float* __restrict__ qkv_b,
             const float* __restrict__ proj_b,
             float* __restrict__ out,
             int nW)
{
    const int t = threadIdx.x, wid = t >> 5, lane = t & 31, b = blockIdx.x;
    const uint32_t sb = smem_u32(smc);
    const int mt = wid & 3;      // m tile 0..3
    const int g6 = wid >> 2;     // n group 0..1 -> heads 3*g6..3*g6+2

    // ---- stage x: coalesced LDG.128 -> packed fp16 X plane ----
    {
        const float4* xb4 = (const float4*)(x + (size_t)b * 6144);
        #pragma unroll
        for (int i = 0; i < 6; i++) {
            int e4 = t + i * THREADS;            // 1536 float4
            int row = e4 / 24, c4 = e4 % 24;
            float4 v = xb4[e4];
            uint2 p;
            p.x = packh(v.x, v.y);
            p.y = packh(v.z, v.w);
            *(uint2*)(smc + XP_OFF + (uint32_t)row * PITCHB + c4 * 8) = p;
        }
    }
    __syncthreads();

    // ---- load A fragments from X plane (conflict-free ldsm) ----
    uint32_t xah[6][4];
    #pragma unroll
    for (int kt = 0; kt < 6; kt++) {
        uint32_t ar = (uint32_t)(mt * 16 + (lane & 15)) * PITCHB
                    + (uint32_t)(kt * 16 + ((lane >> 4) << 3)) * 2;
        ldsm_x4(xah[kt], sb + XP_OFF + ar);
    }
    const int r0 = mt * 16 + (lane >> 2);

    // ---- q slice (s=0): accumulators stay in registers as A-fragments ----
    uint32_t qfrag[3][4];
    {
        float acc[6][4];
        #pragma unroll
        for (int j = 0; j < 6; j++)
            { acc[j][0] = 0.f; acc[j][1] = 0.f; acc[j][2] = 0.f; acc[j][3] = 0.f; }
        #pragma unroll
        for (int kt = 0; kt < 6; kt++) {
            #pragma unroll
            for (int jp = 0; jp < 3; jp++) {
                int fi = (kt * 6 + g6 * 3 + jp) * 32 + lane;
                uint4 w = g_qwf4[fi];
                mma_h(acc[2*jp],   xah[kt], w.x, w.y);
                mma_h(acc[2*jp+1], xah[kt], w.z, w.w);
            }
        }
        const float QBS = 0.25f * LOG2E;
        #pragma unroll
        for (int iu = 0; iu < 3; iu++) {
            int c0 = (g6 * 6 + 2 * iu) * 8 + (lane & 3) * 2;
            float b0 = __ldg(qkv_b + c0)     * QBS;
            float b1 = __ldg(qkv_b + c0 + 1) * QBS;
            float b2 = __ldg(qkv_b + c0 + 8) * QBS;
            float b3 = __ldg(qkv_b + c0 + 9) * QBS;
            qfrag[iu][0] = packh(acc[2*iu][0]   + b0, acc[2*iu][1]   + b1);
            qfrag[iu][1] = packh(acc[2*iu][2]   + b0, acc[2*iu][3]   + b1);
            qfrag[iu][2] = packh(acc[2*iu+1][0] + b2, acc[2*iu+1][1] + b3);
            qfrag[iu][3] = packh(acc[2*iu+1][2] + b2, acc[2*iu+1][3] + b3);
        }
    }

    // ---- k,v slices (s=1,2): store to smem planes ----
    #pragma unroll 1
    for (int s = 1; s < 3; s++) {
        float acc[6][4];
        #pragma unroll
        for (int j = 0; j < 6; j++)
            { acc[j][0] = 0.f; acc[j][1] = 0.f; acc[j][2] = 0.f; acc[j][3] = 0.f; }
        #pragma unroll
        for (int kt = 0; kt < 6; kt++) {
            #pragma unroll
            for (int jp = 0; jp < 3; jp++) {
                int fi = ((s * 6 + kt) * 6 + g6 * 3 + jp) * 32 + lane;
                uint4 w = g_qwf4[fi];
                mma_h(acc[2*jp],   xah[kt], w.x, w.y);
                mma_h(acc[2*jp+1], xah[kt], w.z, w.w);
            }
        }
        const uint32_t pofs = (s == 1) ? KP_OFF : VP_OFF;
        #pragma unroll
        for (int j = 0; j < 6; j++) {
            int c0 = (g6 * 6 + j) * 8 + (lane & 3) * 2;
            float b0 = __ldg(qkv_b + s * 96 + c0), b1 = __ldg(qkv_b + s * 96 + c0 + 1);
            uint32_t off = (uint32_t)r0 * PITCHB + c0 * 2;
            *(uint32_t*)(smc + pofs + off) = packh(acc[j][0] + b0, acc[j][1] + b1);
            *(uint32_t*)(smc + pofs + off + 8 * PITCHB) = packh(acc[j][2] + b0, acc[j][3] + b1);
        }
    }
    __syncthreads();   // k/v complete; X reads done

    // ---- preload mask fragments (h-independent, reused across 3 units) ----
    uint2 mreg[8];
    {
        const uint2* mfp = g_maskf + ((size_t)(b % nW) * 4 + mt) * 256 + lane;
        #pragma unroll
        for (int nt = 0; nt < 8; nt++) mreg[nt] = mfp[nt * 32];
    }

    // ---- attention: warp handles heads 3*g6 + {0,1,2} on its mt tile ----
    uint32_t oah[3][4];              // own O tiles in proj-A fragment form
    #pragma unroll 1
    for (int iu = 0; iu < 3; iu++) {
        const int h = 3 * g6 + iu;

        float s8[8][4];
        #pragma unroll
        for (int ntp = 0; ntp < 4; ntp++) {
            uint32_t kh[4];
            uint32_t br = (uint32_t)(ntp * 16 + (lane & 15)) * PITCHB
                        + (uint32_t)(h * 16 + ((lane >> 4) << 3)) * 2;
            ldsm_x4(kh, sb + KP_OFF + br);
            #pragma unroll
            for (int half = 0; half < 2; half++) {
                int nt = 2 * ntp + half;
                s8[nt][0] = 0.f; s8[nt][1] = 0.f; s8[nt][2] = 0.f; s8[nt][3] = 0.f;
                mma_h(s8[nt], qfrag[iu], kh[half], kh[half + 2]);
            }
        }
        // + (bias + mask) in log2 domain; bare ex2 (no max-shift: |arg| << 126)
        float sum0 = 0.f, sum1 = 0.f;
        {
            const uint2* bfp = g_biasf + ((size_t)h * 4 + mt) * 256 + lane;
            #pragma unroll
            for (int nt = 0; nt < 8; nt++) {
                uint2 bw = bfp[nt * 32];
                __half2 a0 = __hadd2(*reinterpret_cast<__half2*>(&bw.x),
                                     *reinterpret_cast<__half2*>(&mreg[nt].x));
                __half2 a1 = __hadd2(*reinterpret_cast<__half2*>(&bw.y),
                                     *reinterpret_cast<__half2*>(&mreg[nt].y));
                float2 f0 = __half22float2(a0);
                float2 f1 = __half22float2(a1);
                s8[nt][0] = ex2f(s8[nt][0] + f0.x); sum0 += s8[nt][0];
                s8[nt][1] = ex2f(s8[nt][1] + f0.y); sum0 += s8[nt][1];
                s8[nt][2] = ex2f(s8[nt][2] + f1.x); sum1 += s8[nt][2];
                s8[nt][3] = ex2f(s8[nt][3] + f1.y); sum1 += s8[nt][3];
            }
        }
        sum0 += __shfl_xor_sync(0xffffffffu, sum0, 1);
        sum0 += __shfl_xor_sync(0xffffffffu, sum0, 2);
        sum1 += __shfl_xor_sync(0xffffffffu, sum1, 1);
        sum1 += __shfl_xor_sync(0xffffffffu, sum1, 2);
        float inv0 = 1.f / sum0, inv1 = 1.f / sum1;

        // PV with UNNORMALIZED P (fold 1/sum into O accumulators afterwards)
        float o[2][4];
        o[0][0]=0.f;o[0][1]=0.f;o[0][2]=0.f;o[0][3]=0.f;
        o[1][0]=0.f;o[1][1]=0.f;o[1][2]=0.f;o[1][3]=0.f;
        #pragma unroll
        for (int kt = 0; kt < 4; kt++) {
            uint32_t pa[4];
            pa[0] = packh(s8[2*kt][0],   s8[2*kt][1]);
            pa[1] = packh(s8[2*kt][2],   s8[2*kt][3]);
            pa[2] = packh(s8[2*kt+1][0], s8[2*kt+1][1]);
            pa[3] = packh(s8[2*kt+1][2], s8[2*kt+1][3]);
            uint32_t vr = (uint32_t)(kt * 16 + (lane & 15)) * PITCHB
                        + (uint32_t)(h * 16 + ((lane >> 4) << 3)) * 2;
            uint32_t vh[4];
            ldsm_x4t(vh, sb + VP_OFF + vr);
            mma_h(o[0], pa, vh[0], vh[1]);
            mma_h(o[1], pa, vh[2], vh[3]);
        }
        // normalize O rows (r0 -> inv0, r0+8 -> inv1), pack, keep + share
        #pragma unroll
        for (int nt2 = 0; nt2 < 2; nt2++) {
            int c0 = h * 16 + nt2 * 8 + (lane & 3) * 2;
            uint32_t p0 = packh(o[nt2][0] * inv0, o[nt2][1] * inv0);
            uint32_t p1 = packh(o[nt2][2] * inv1, o[nt2][3] * inv1);
            oah[iu][nt2*2]   = p0;
            oah[iu][nt2*2+1] = p1;
            uint32_t off = (uint32_t)r0 * PITCHB + c0 * 2;
            *(uint32_t*)(smc + XP_OFF + off)              = p0;
            *(uint32_t*)(smc + XP_OFF + off + 8 * PITCHB) = p1;
        }
    }
    __syncthreads();   // O complete; K/V planes now dead

    // ---- proj GEMM: A = O single fp16 (own tiles: kt in [3*g6, 3*g6+2]) ----
    {
        float acc[6][4];
        #pragma unroll
        for (int j = 0; j < 6; j++)
            { acc[j][0] = 0.f; acc[j][1] = 0.f; acc[j][2] = 0.f; acc[j][3] = 0.f; }
        #pragma unroll
        for (int kt = 0; kt < 6; kt++) {
            uint32_t ah[4];
            if (kt / 3 == g6) {
                int iu = kt - 3 * g6;
                ah[0] = oah[iu][0]; ah[1] = oah[iu][1]; ah[2] = oah[iu][2]; ah[3] = oah[iu][3];
            } else {
                uint32_t ar = (uint32_t)(mt * 16 + (lane & 15)) * PITCHB
                            + (uint32_t)(kt * 16 + ((lane >> 4) << 3)) * 2;
                ldsm_x4(ah, sb + XP_OFF + ar);
            }
            #pragma unroll
            for (int jp = 0; jp < 3; jp++) {
                int fi = (kt * 6 + g6 * 3 + jp) * 32 + lane;
                uint4 w = g_pwf4[fi];
                mma_h(acc[2*jp],   ah, w.x, w.y);
                mma_h(acc[2*jp+1], ah, w.z, w.w);
            }
        }
        // stage fp32 results (+bias) into dead K/V region (pitch 104 floats)
        float* stg = (float*)(smc + KP_OFF);
        #pragma unroll
        for (int j = 0; j < 6; j++) {
            int c0 = (g6 * 6 + j) * 8 + (lane & 3) * 2;
            float b0 = __ldg(proj_b + c0), b1 = __ldg(proj_b + c0 + 1);
            *(float2*)(stg + (uint32_t)r0 * 104 + c0) =
                make_float2(acc[j][0] + b0, acc[j][1] + b1);
            *(float2*)(stg + (uint32_t)(r0 + 8) * 104 + c0) =
                make_float2(acc[j][2] + b0, acc[j][3] + b1);
        }
    }
    __syncthreads();

    // ---- coalesced output copy ----
    {
        const float* stg = (const float*)(smc + KP_OFF);
        float4* ob4 = (float4*)(out + (size_t)b * 6144);
        #pragma unroll
        for (int i = 0; i < 6; i++) {
            int e4 = t + i * THREADS;            // 1536 float4
            int row = e4 / 24, c4 = e4 % 24;
            ob4[e4] = *(const float4*)(stg + (uint32_t)row * 104 + c4 * 4);
        }
    }
}

extern "C" void kernel_launch(void* const* d_in, const int* in_sizes, int n_in,
                              void* d_out, int out_size) {
    const float* x      = (const float*)d_in[0];
    const float* mask   = (const float*)d_in[1];
    const float* qkv_w  = (const float*)d_in[2];
    const float* qkv_b  = (const float*)d_in[3];
    const float* proj_w = (const float*)d_in[4];
    const float* proj_b = (const float*)d_in[5];
    const float* rpb    = (const float*)d_in[6];
    const int*   ridx   = (const int*)d_in[7];
    float* out = (float*)d_out;

    const int B_ = in_sizes[0] / (N_TOK * DIM);        // 8192
    const int nW = in_sizes[1] / (N_TOK * N_TOK);      // 512

    int prep_total = 4608 + 6144 + nW * 1024;
    prep_kernel<<<(prep_total + 255) / 256, 256>>>(qkv_w, proj_w, rpb, ridx,
                                                   mask, nW);

    cudaFuncSetAttribute(win_attn_mma,
                         cudaFuncAttributeMaxDynamicSharedMemorySize, SMEM_BYTES);
    win_attn_mma<<<B_, THREADS, SMEM_BYTES>>>(x, qkv_b, proj_b, out, nW);
}